// round 4
// baseline (speedup 1.0000x reference)
#include <cuda_runtime.h>
#include <cuda_bf16.h>

#define Bb   8
#define T    16
#define C    64
#define Hh   56
#define Ww   56
#define HW   3136          // 56*56
#define HW4  784           // HW/4
#define DIN  64            // 8*8 pooled
#define DOUT 32            // 2*d_t
#define NBC  512           // b*c
#define NT   (NBC * T)     // 8192 (n,t) slices
#define NCOL (NBC * HW4)   // 401408 float4 columns total (= 1568 * 256)

// scratch
__device__ float g_flat[NT * DIN];       // pooled features [n*T+t][64], 2MB
__device__ float g_att[NBC * T * T];     // softmaxed attention, 512KB

typedef unsigned long long u64;

__device__ __forceinline__ u64 fma2(u64 a, u64 b, u64 c) {
    u64 d;
    asm("fma.rn.f32x2 %0, %1, %2, %3;" : "=l"(d) : "l"(a), "l"(b), "l"(c));
    return d;
}
__device__ __forceinline__ u64 pack2(float lo, float hi) {
    u64 d;
    asm("mov.b64 %0, {%1, %2};" : "=l"(d) : "r"(__float_as_uint(lo)), "r"(__float_as_uint(hi)));
    return d;
}

// ---------------------------------------------------------------------------
// Kernel 1: pooling. One block per (n,t) slice: 56x56 -> 8x8 (7x7 mean bins).
// ---------------------------------------------------------------------------
__global__ __launch_bounds__(256)
void pool_kernel(const float* __restrict__ x)
{
    const int nt  = blockIdx.x;        // n*T + t
    const int n   = nt >> 4;
    const int t   = nt & 15;
    const int b   = n >> 6;
    const int c   = n & 63;
    const int tid = threadIdx.x;

    __shared__ float sx[HW];           // 12.5 KB

    const float4* xp4 =
        (const float4*)(x + ((size_t)(b * T + t) * C + c) * HW);
    #pragma unroll
    for (int i = tid; i < HW4; i += 256)
        ((float4*)sx)[i] = xp4[i];
    __syncthreads();

    if (tid < 64) {
        const int d1 = tid >> 3, d2 = tid & 7;
        const float* row = sx + (7 * d1) * Ww + 7 * d2;
        float s = 0.f;
        #pragma unroll
        for (int dh = 0; dh < 7; ++dh)
            #pragma unroll
            for (int dw = 0; dw < 7; ++dw)
                s += row[dh * Ww + dw];
        g_flat[nt * DIN + tid] = s * (1.f / 49.f);
    }
}

// ---------------------------------------------------------------------------
// Kernel 2: q/k projection + att + softmax. One block per n. Tiny.
// ---------------------------------------------------------------------------
__global__ __launch_bounds__(256)
void att_kernel(const float* __restrict__ Wq, const float* __restrict__ bq,
                const float* __restrict__ Wk, const float* __restrict__ bk)
{
    const int n   = blockIdx.x;
    const int tid = threadIdx.x;

    __shared__ float flat[T][DIN];           // 4 KB
    __shared__ float sWq[DIN * DOUT];        // 8 KB
    __shared__ float sWk[DIN * DOUT];        // 8 KB
    __shared__ float sq[T][DOUT + 1];
    __shared__ float sk[T][DOUT + 1];
    __shared__ float satt[T][T + 1];

    for (int i = tid; i < DIN * DOUT; i += 256) {
        sWq[i] = Wq[i];
        sWk[i] = Wk[i];
    }
    for (int i = tid; i < T * DIN; i += 256)
        ((float*)flat)[i] = g_flat[n * T * DIN + i];
    __syncthreads();

    for (int i = tid; i < T * DOUT; i += 256) {
        const int tt = i >> 5, j = i & 31;
        float aq = bq[j];
        float ak = bk[j];
        #pragma unroll
        for (int d = 0; d < DIN; ++d) {
            const float f = flat[tt][d];
            aq = fmaf(f, sWq[d * DOUT + j], aq);
            ak = fmaf(f, sWk[d * DOUT + j], ak);
        }
        sq[tt][j] = aq;
        sk[tt][j] = ak;
    }
    __syncthreads();

    {
        const int i = tid >> 4, j = tid & 15;
        float s = 0.f;
        #pragma unroll
        for (int d = 0; d < DOUT; ++d)
            s = fmaf(sq[i][d], sk[j][d], s);
        satt[i][j] = s * 0.25f;                // 1/sqrt(16)
    }
    __syncthreads();

    if (tid < T) {
        const int i = tid;
        float m = -1e30f;
        #pragma unroll
        for (int j = 0; j < T; ++j) m = fmaxf(m, satt[i][j]);
        float e[T];
        float ssum = 0.f;
        #pragma unroll
        for (int j = 0; j < T; ++j) {
            e[j] = __expf(satt[i][j] - m);
            ssum += e[j];
        }
        const float inv = 1.f / ssum;
        #pragma unroll
        for (int j = 0; j < T; ++j)
            g_att[n * (T * T) + i * T + j] = e[j] * inv;
    }
}

// ---------------------------------------------------------------------------
// Kernel 3: out[b,t,c,:] = sum_s att[n,t,s] * x[b,s,c,:]
// Globally flattened: exactly 1568 full blocks, zero dead threads.
// Inner math uses packed fma.rn.f32x2 (FFMA2) -> half the FMA instructions.
// att weights pre-duplicated into both f32x2 lanes in smem.
// ---------------------------------------------------------------------------
__global__ __launch_bounds__(256)
void av_kernel(const float* __restrict__ x, float* __restrict__ out)
{
    const int tid  = threadIdx.x;
    const int gid0 = blockIdx.x << 8;               // first column of block
    const int n0   = gid0 / HW4;                    // block spans n0 or n0+1

    // stage att for the (at most) 2 n's this block touches, duplicated pairs
    __shared__ u64 satt[2][T * T];
    #pragma unroll
    for (int i = tid; i < 2 * T * T; i += 256) {
        const int m   = i >> 8;
        const int idx = i & 255;
        const int nn  = n0 + m;
        const float a = (nn < NBC) ? g_att[nn * (T * T) + idx] : 0.f;
        satt[m][idx] = pack2(a, a);
    }
    __syncthreads();

    const int gid = gid0 + tid;
    const int n   = gid / HW4;
    const int p4  = gid - n * HW4;
    const int m   = n - n0;
    const int b   = n >> 6;
    const int c   = n & 63;

    const size_t stride_s = (size_t)C * HW4;        // float4 stride per t/s
    const ulonglong2* xb = (const ulonglong2*)x
                         + ((size_t)b * T * C + c) * HW4 + p4;
    ulonglong2* ob = (ulonglong2*)out
                   + ((size_t)b * T * C + c) * HW4 + p4;

    u64 v0[T], v1[T];
    #pragma unroll
    for (int s = 0; s < T; ++s) {
        const ulonglong2 q = xb[s * stride_s];
        v0[s] = q.x;
        v1[s] = q.y;
    }

    const u64* arow = satt[m];
    #pragma unroll
    for (int t = 0; t < T; ++t) {
        u64 a0 = 0ull, a1 = 0ull;                   // packed {0.f, 0.f}
        #pragma unroll
        for (int s = 0; s < T; ++s) {
            const u64 w2 = arow[t * T + s];
            a0 = fma2(w2, v0[s], a0);
            a1 = fma2(w2, v1[s], a1);
        }
        ulonglong2 r; r.x = a0; r.y = a1;
        __stcs(&ob[t * stride_s], r);               // streaming store
    }
}

// ---------------------------------------------------------------------------
extern "C" void kernel_launch(void* const* d_in, const int* in_sizes, int n_in,
                              void* d_out, int out_size)
{
    const float* x  = (const float*)d_in[0];
    const float* Wq = (const float*)d_in[1];
    const float* bq = (const float*)d_in[2];
    const float* Wk = (const float*)d_in[3];
    const float* bk = (const float*)d_in[4];
    float* out = (float*)d_out;

    pool_kernel<<<NT, 256>>>(x);
    att_kernel<<<NBC, 256>>>(Wq, bq, Wk, bk);
    av_kernel<<<NCOL / 256, 256>>>(x, out);
}

// round 5
// speedup vs baseline: 1.0489x; 1.0489x over previous
#include <cuda_runtime.h>
#include <cuda_bf16.h>

#define Bb   8
#define T    16
#define C    64
#define Hh   56
#define Ww   56
#define HW   3136          // 56*56
#define HW4  784           // HW/4
#define DIN  64            // 8*8 pooled
#define DOUT 32            // 2*d_t
#define NBC  512           // b*c
#define NT   (NBC * T)     // 8192 (n,t) slices
#define NCOL (NBC * HW4)   // 401408 float4 columns total (= 1568 * 256)

// scratch
__device__ float g_flat[NT * DIN];       // pooled features [n*T+t][64], 2MB
__device__ float g_att[NBC * T * T];     // softmaxed attention, 512KB

// ---------------------------------------------------------------------------
// Kernel 1: pooling. One block per (n, t-pair): two 56x56 slices -> 2x(8x8).
// 4096 blocks; ~6 independent float4 LDGs per thread (higher MLP than 1-slice).
// ---------------------------------------------------------------------------
__global__ __launch_bounds__(256)
void pool_kernel(const float* __restrict__ x)
{
    const int blk = blockIdx.x;        // 0..4095
    const int n   = blk >> 3;
    const int t0  = (blk & 7) << 1;    // first of two t's
    const int b   = n >> 6;
    const int c   = n & 63;
    const int tid = threadIdx.x;

    __shared__ float sx[2 * HW];       // 25 KB

    const float4* xp0 =
        (const float4*)(x + ((size_t)(b * T + t0) * C + c) * HW);
    const float4* xp1 =
        (const float4*)(x + ((size_t)(b * T + t0 + 1) * C + c) * HW);
    float4* s0 = (float4*)sx;
    float4* s1 = (float4*)(sx + HW);
    #pragma unroll
    for (int i = tid; i < HW4; i += 256) {
        s0[i] = xp0[i];
        s1[i] = xp1[i];
    }
    __syncthreads();

    if (tid < 128) {
        const int sl  = tid >> 6;            // which slice
        const int bin = tid & 63;
        const int d1 = bin >> 3, d2 = bin & 7;
        const float* row = sx + sl * HW + (7 * d1) * Ww + 7 * d2;
        float s = 0.f;
        #pragma unroll
        for (int dh = 0; dh < 7; ++dh)
            #pragma unroll
            for (int dw = 0; dw < 7; ++dw)
                s += row[dh * Ww + dw];
        g_flat[(n * T + t0 + sl) * DIN + bin] = s * (1.f / 49.f);
    }
}

// ---------------------------------------------------------------------------
// Kernel 2: q/k projection + att + softmax. One block per n. Tiny.
// ---------------------------------------------------------------------------
__global__ __launch_bounds__(256)
void att_kernel(const float* __restrict__ Wq, const float* __restrict__ bq,
                const float* __restrict__ Wk, const float* __restrict__ bk)
{
    const int n   = blockIdx.x;
    const int tid = threadIdx.x;

    __shared__ float flat[T][DIN];           // 4 KB
    __shared__ float sWq[DIN * DOUT];        // 8 KB
    __shared__ float sWk[DIN * DOUT];        // 8 KB
    __shared__ float sq[T][DOUT + 1];
    __shared__ float sk[T][DOUT + 1];
    __shared__ float satt[T][T + 1];

    for (int i = tid; i < DIN * DOUT; i += 256) {
        sWq[i] = Wq[i];
        sWk[i] = Wk[i];
    }
    for (int i = tid; i < T * DIN; i += 256)
        ((float*)flat)[i] = g_flat[n * T * DIN + i];
    __syncthreads();

    for (int i = tid; i < T * DOUT; i += 256) {
        const int tt = i >> 5, j = i & 31;
        float aq = bq[j];
        float ak = bk[j];
        #pragma unroll
        for (int d = 0; d < DIN; ++d) {
            const float f = flat[tt][d];
            aq = fmaf(f, sWq[d * DOUT + j], aq);
            ak = fmaf(f, sWk[d * DOUT + j], ak);
        }
        sq[tt][j] = aq;
        sk[tt][j] = ak;
    }
    __syncthreads();

    {
        const int i = tid >> 4, j = tid & 15;
        float s = 0.f;
        #pragma unroll
        for (int d = 0; d < DOUT; ++d)
            s = fmaf(sq[i][d], sk[j][d], s);
        satt[i][j] = s * 0.25f;                // 1/sqrt(16)
    }
    __syncthreads();

    if (tid < T) {
        const int i = tid;
        float m = -1e30f;
        #pragma unroll
        for (int j = 0; j < T; ++j) m = fmaxf(m, satt[i][j]);
        float e[T];
        float ssum = 0.f;
        #pragma unroll
        for (int j = 0; j < T; ++j) {
            e[j] = __expf(satt[i][j] - m);
            ssum += e[j];
        }
        const float inv = 1.f / ssum;
        #pragma unroll
        for (int j = 0; j < T; ++j)
            g_att[n * (T * T) + i * T + j] = e[j] * inv;
    }
}

// ---------------------------------------------------------------------------
// Kernel 3: out[b,t,c,:] = sum_s att[n,t,s] * x[b,s,c,:]
// Globally flattened: exactly 1568 full blocks, zero dead threads.
// Scalar float4 FMA (proven codegen), streaming stores keep x in L2.
// ---------------------------------------------------------------------------
__global__ __launch_bounds__(256)
void av_kernel(const float* __restrict__ x, float* __restrict__ out)
{
    const int tid  = threadIdx.x;
    const int gid0 = blockIdx.x << 8;               // first column of block
    const int n0   = gid0 / HW4;                    // block spans n0 or n0+1

    // stage att for the (at most) 2 n's this block touches
    __shared__ float satt[2][T * T];
    #pragma unroll
    for (int i = tid; i < 2 * T * T; i += 256) {
        const int m   = i >> 8;
        const int idx = i & 255;
        const int nn  = n0 + m;
        satt[m][idx] = (nn < NBC) ? g_att[nn * (T * T) + idx] : 0.f;
    }
    __syncthreads();

    const int gid = gid0 + tid;
    const int n   = gid / HW4;
    const int p4  = gid - n * HW4;
    const int m   = n - n0;
    const int b   = n >> 6;
    const int c   = n & 63;

    const size_t stride_s = (size_t)C * HW4;        // float4 stride per t/s
    const float4* xb = (const float4*)x
                     + ((size_t)b * T * C + c) * HW4 + p4;
    float4* ob = (float4*)out
               + ((size_t)b * T * C + c) * HW4 + p4;

    float4 v[T];
    #pragma unroll
    for (int s = 0; s < T; ++s)
        v[s] = xb[s * stride_s];

    const float* arow = satt[m];
    #pragma unroll
    for (int t = 0; t < T; ++t) {
        float4 a = make_float4(0.f, 0.f, 0.f, 0.f);
        #pragma unroll
        for (int s = 0; s < T; ++s) {
            const float w = arow[t * T + s];
            a.x = fmaf(w, v[s].x, a.x);
            a.y = fmaf(w, v[s].y, a.y);
            a.z = fmaf(w, v[s].z, a.z);
            a.w = fmaf(w, v[s].w, a.w);
        }
        __stcs(&ob[t * stride_s], a);               // streaming store
    }
}

// ---------------------------------------------------------------------------
extern "C" void kernel_launch(void* const* d_in, const int* in_sizes, int n_in,
                              void* d_out, int out_size)
{
    const float* x  = (const float*)d_in[0];
    const float* Wq = (const float*)d_in[1];
    const float* bq = (const float*)d_in[2];
    const float* Wk = (const float*)d_in[3];
    const float* bk = (const float*)d_in[4];
    float* out = (float*)d_out;

    pool_kernel<<<NT / 2, 256>>>(x);
    att_kernel<<<NBC, 256>>>(Wq, bq, Wk, bk);
    av_kernel<<<NCOL / 256, 256>>>(x, out);
}

// round 6
// speedup vs baseline: 1.1324x; 1.0796x over previous
#include <cuda_runtime.h>
#include <cuda_bf16.h>

#define Bb   8
#define T    16
#define C    64
#define Hh   56
#define Ww   56
#define HW   3136          // 56*56
#define HW4  784           // HW/4
#define DIN  64            // 8*8 pooled
#define DOUT 32            // 2*d_t
#define NBC  512           // b*c
#define NT   (NBC * T)     // 8192 (n,t) slices
#define NCOL (NBC * HW4)   // 401408 float4 columns total (= 1568 * 256)

// scratch
__device__ float g_flat[NT * DIN];       // pooled features [n*T+t][64], 2MB
__device__ float g_att[NBC * T * T];     // softmaxed attention, 512KB

// ---------------------------------------------------------------------------
// Kernel 1: pooling. One block per (n,t) slice: 56x56 -> 8x8 (7x7 mean bins).
// Reduce parallelized over ALL 256 threads: 4 threads per bin (rows 0-1 / 2-3
// / 4-5 / 6), then 2 shfl_xor combines within each lane-quad.
// ---------------------------------------------------------------------------
__global__ __launch_bounds__(256)
void pool_kernel(const float* __restrict__ x)
{
    const int nt  = blockIdx.x;        // n*T + t
    const int n   = nt >> 4;
    const int t   = nt & 15;
    const int b   = n >> 6;
    const int c   = n & 63;
    const int tid = threadIdx.x;

    __shared__ float sx[HW];           // 12.5 KB

    const float4* xp4 =
        (const float4*)(x + ((size_t)(b * T + t) * C + c) * HW);
    #pragma unroll
    for (int i = tid; i < HW4; i += 256)
        ((float4*)sx)[i] = xp4[i];
    __syncthreads();

    // 4 threads per bin: part p handles rows {2p, 2p+1} (part 3: row 6 only)
    const int bin  = tid >> 2;          // 0..63
    const int part = tid & 3;           // 0..3
    const int d1 = bin >> 3, d2 = bin & 7;
    const float* base = sx + (7 * d1) * Ww + 7 * d2;

    float s = 0.f;
    const int r0 = 2 * part;
    {
        const float* row = base + r0 * Ww;
        #pragma unroll
        for (int dw = 0; dw < 7; ++dw) s += row[dw];
    }
    if (part < 3) {
        const float* row = base + (r0 + 1) * Ww;
        #pragma unroll
        for (int dw = 0; dw < 7; ++dw) s += row[dw];
    }
    // combine the 4 partials within each lane-quad
    s += __shfl_xor_sync(0xffffffffu, s, 1);
    s += __shfl_xor_sync(0xffffffffu, s, 2);
    if (part == 0)
        g_flat[nt * DIN + bin] = s * (1.f / 49.f);
}

// ---------------------------------------------------------------------------
// Kernel 2: q/k projection + att + register/shuffle softmax. One block per n.
// ---------------------------------------------------------------------------
__global__ __launch_bounds__(256)
void att_kernel(const float* __restrict__ Wq, const float* __restrict__ bq,
                const float* __restrict__ Wk, const float* __restrict__ bk)
{
    const int n   = blockIdx.x;
    const int tid = threadIdx.x;

    __shared__ float flat[T][DIN];           // 4 KB
    __shared__ float sWq[DIN * DOUT];        // 8 KB
    __shared__ float sWk[DIN * DOUT];        // 8 KB
    __shared__ float sq[T][DOUT + 1];
    __shared__ float sk[T][DOUT + 1];

    for (int i = tid; i < DIN * DOUT; i += 256) {
        sWq[i] = Wq[i];
        sWk[i] = Wk[i];
    }
    for (int i = tid; i < T * DIN; i += 256)
        ((float*)flat)[i] = g_flat[n * T * DIN + i];
    __syncthreads();

    // q = flat@Wq + bq ; k = flat@Wk + bk (2 outputs per thread)
    for (int i = tid; i < T * DOUT; i += 256) {
        const int tt = i >> 5, j = i & 31;
        float aq = bq[j];
        float ak = bk[j];
        #pragma unroll
        for (int d = 0; d < DIN; ++d) {
            const float f = flat[tt][d];
            aq = fmaf(f, sWq[d * DOUT + j], aq);
            ak = fmaf(f, sWk[d * DOUT + j], ak);
        }
        sq[tt][j] = aq;
        sk[tt][j] = ak;
    }
    __syncthreads();

    // logit[i][j] in register of thread tid = i*16 + j
    const int i = tid >> 4, j = tid & 15;
    float s = 0.f;
    #pragma unroll
    for (int d = 0; d < DOUT; ++d)
        s = fmaf(sq[i][d], sk[j][d], s);
    s *= 0.25f;                          // 1/sqrt(16)

    // row softmax via 16-lane shuffle groups (lanes of same i are contiguous)
    float m = s;
    #pragma unroll
    for (int k = 8; k >= 1; k >>= 1)
        m = fmaxf(m, __shfl_xor_sync(0xffffffffu, m, k));
    float e = __expf(s - m);
    float ssum = e;
    #pragma unroll
    for (int k = 8; k >= 1; k >>= 1)
        ssum += __shfl_xor_sync(0xffffffffu, ssum, k);

    g_att[n * (T * T) + tid] = e * (1.f / ssum);
}

// ---------------------------------------------------------------------------
// Kernel 3: out[b,t,c,:] = sum_s att[n,t,s] * x[b,s,c,:]
// Globally flattened: exactly 1568 full blocks, zero dead threads.
// Scalar float4 FMA, streaming stores keep x resident in L2.
// ---------------------------------------------------------------------------
__global__ __launch_bounds__(256)
void av_kernel(const float* __restrict__ x, float* __restrict__ out)
{
    const int tid  = threadIdx.x;
    const int gid0 = blockIdx.x << 8;               // first column of block
    const int n0   = gid0 / HW4;                    // block spans n0 or n0+1

    // stage att for the (at most) 2 n's this block touches
    __shared__ float satt[2][T * T];
    #pragma unroll
    for (int i = tid; i < 2 * T * T; i += 256) {
        const int m   = i >> 8;
        const int idx = i & 255;
        const int nn  = n0 + m;
        satt[m][idx] = (nn < NBC) ? g_att[nn * (T * T) + idx] : 0.f;
    }
    __syncthreads();

    const int gid = gid0 + tid;
    const int n   = gid / HW4;
    const int p4  = gid - n * HW4;
    const int m   = n - n0;
    const int b   = n >> 6;
    const int c   = n & 63;

    const int stride_s = C * HW4;                   // float4 stride per t/s
    const int base     = (b * T * C + c) * HW4 + p4;
    const float4* xb = (const float4*)x + base;
    float4* ob = (float4*)out + base;

    float4 v[T];
    #pragma unroll
    for (int s = 0; s < T; ++s)
        v[s] = xb[s * stride_s];

    const float* arow = satt[m];
    #pragma unroll
    for (int t = 0; t < T; ++t) {
        float4 a = make_float4(0.f, 0.f, 0.f, 0.f);
        #pragma unroll
        for (int s = 0; s < T; ++s) {
            const float w = arow[t * T + s];
            a.x = fmaf(w, v[s].x, a.x);
            a.y = fmaf(w, v[s].y, a.y);
            a.z = fmaf(w, v[s].z, a.z);
            a.w = fmaf(w, v[s].w, a.w);
        }
        __stcs(&ob[t * stride_s], a);               // streaming store
    }
}

// ---------------------------------------------------------------------------
extern "C" void kernel_launch(void* const* d_in, const int* in_sizes, int n_in,
                              void* d_out, int out_size)
{
    const float* x  = (const float*)d_in[0];
    const float* Wq = (const float*)d_in[1];
    const float* bq = (const float*)d_in[2];
    const float* Wk = (const float*)d_in[3];
    const float* bk = (const float*)d_in[4];
    float* out = (float*)d_out;

    pool_kernel<<<NT, 256>>>(x);
    att_kernel<<<NBC, 256>>>(Wq, bq, Wk, bk);
    av_kernel<<<NCOL / 256, 256>>>(x, out);
}

// round 7
// speedup vs baseline: 1.2754x; 1.1263x over previous
#include <cuda_runtime.h>
#include <cuda_bf16.h>

#define Bb   8
#define T    16
#define C    64
#define Hh   56
#define Ww   56
#define HW   3136          // 56*56
#define HW4  784           // HW/4
#define DIN  64            // 8*8 pooled
#define DOUT 32            // 2*d_t
#define NBC  512           // b*c
#define NT   (NBC * T)     // 8192 (n,t) slices
#define NCOL (NBC * HW4)   // 401408 float4 columns total (= 1568 * 256)

// scratch
__device__ float g_flat[NT * DIN];       // pooled features [n*T+t][64], 2MB
__device__ float g_att[NBC * T * T];     // softmaxed attention, 512KB

// ---------------------------------------------------------------------------
// Kernel 1: pooling. One block per (n,t) slice: 56x56 -> 8x8 (7x7 mean bins).
// Serial 64-thread reduce (proven fastest), 4 independent accumulators to
// break the FADD dependency chain.
// ---------------------------------------------------------------------------
__global__ __launch_bounds__(256)
void pool_kernel(const float* __restrict__ x)
{
    const int nt  = blockIdx.x;        // n*T + t
    const int n   = nt >> 4;
    const int t   = nt & 15;
    const int b   = n >> 6;
    const int c   = n & 63;
    const int tid = threadIdx.x;

    __shared__ float sx[HW];           // 12.5 KB

    const float4* xp4 =
        (const float4*)(x + ((size_t)(b * T + t) * C + c) * HW);
    #pragma unroll
    for (int i = tid; i < HW4; i += 256)
        ((float4*)sx)[i] = xp4[i];
    __syncthreads();

    if (tid < 64) {
        const int d1 = tid >> 3, d2 = tid & 7;
        const float* base = sx + (7 * d1) * Ww + 7 * d2;
        float a0 = 0.f, a1 = 0.f, a2 = 0.f, a3 = 0.f;
        #pragma unroll
        for (int dh = 0; dh < 7; ++dh) {
            const float* row = base + dh * Ww;
            a0 += row[0];
            a1 += row[1];
            a2 += row[2];
            a3 += row[3];
            a0 += row[4];
            a1 += row[5];
            a2 += row[6];
        }
        g_flat[nt * DIN + tid] = (a0 + a1 + a2 + a3) * (1.f / 49.f);
    }
}

// ---------------------------------------------------------------------------
// Kernel 2: q/k projection + att + register/shuffle softmax. One block per n.
// ---------------------------------------------------------------------------
__global__ __launch_bounds__(256)
void att_kernel(const float* __restrict__ Wq, const float* __restrict__ bq,
                const float* __restrict__ Wk, const float* __restrict__ bk)
{
    const int n   = blockIdx.x;
    const int tid = threadIdx.x;

    __shared__ float flat[T][DIN];           // 4 KB
    __shared__ float sWq[DIN * DOUT];        // 8 KB
    __shared__ float sWk[DIN * DOUT];        // 8 KB
    __shared__ float sq[T][DOUT + 1];
    __shared__ float sk[T][DOUT + 1];

    for (int i = tid; i < DIN * DOUT; i += 256) {
        sWq[i] = Wq[i];
        sWk[i] = Wk[i];
    }
    for (int i = tid; i < T * DIN; i += 256)
        ((float*)flat)[i] = g_flat[n * T * DIN + i];
    __syncthreads();

    // q = flat@Wq + bq ; k = flat@Wk + bk (2 outputs per thread)
    for (int i = tid; i < T * DOUT; i += 256) {
        const int tt = i >> 5, j = i & 31;
        float aq = bq[j];
        float ak = bk[j];
        #pragma unroll
        for (int d = 0; d < DIN; ++d) {
            const float f = flat[tt][d];
            aq = fmaf(f, sWq[d * DOUT + j], aq);
            ak = fmaf(f, sWk[d * DOUT + j], ak);
        }
        sq[tt][j] = aq;
        sk[tt][j] = ak;
    }
    __syncthreads();

    // logit[i][j] in register of thread tid = i*16 + j
    const int i = tid >> 4, j = tid & 15;
    float s = 0.f;
    #pragma unroll
    for (int d = 0; d < DOUT; ++d)
        s = fmaf(sq[i][d], sk[j][d], s);
    s *= 0.25f;                          // 1/sqrt(16)

    // row softmax via 16-lane shuffle groups (lanes of same i are contiguous)
    float m = s;
    #pragma unroll
    for (int k = 8; k >= 1; k >>= 1)
        m = fmaxf(m, __shfl_xor_sync(0xffffffffu, m, k));
    float e = __expf(s - m);
    float ssum = e;
    #pragma unroll
    for (int k = 8; k >= 1; k >>= 1)
        ssum += __shfl_xor_sync(0xffffffffu, ssum, k);

    g_att[n * (T * T) + tid] = e * (1.f / ssum);
}

// ---------------------------------------------------------------------------
// Kernel 3: out[b,t,c,:] = sum_s att[n,t,s] * x[b,s,c,:]
// Flattened grid (1568 full blocks) traversed in REVERSED n order: pool read
// x ascending, so the tail of x is L2-resident — read it first. __stcs writes
// avoid evicting x.
// ---------------------------------------------------------------------------
__global__ __launch_bounds__(256)
void av_kernel(const float* __restrict__ x, float* __restrict__ out)
{
    const int tid  = threadIdx.x;
    const int gid0 = blockIdx.x << 8;               // first column of block
    const int n0   = gid0 / HW4;                    // block spans n0 or n0+1

    // stage att rows for the (at most) 2 reversed-n's this block touches
    __shared__ float satt[2][T * T];
    #pragma unroll
    for (int i = tid; i < 2 * T * T; i += 256) {
        const int m   = i >> 8;
        const int idx = i & 255;
        const int nn  = n0 + m;
        satt[m][idx] = (nn < NBC) ? g_att[(NBC - 1 - nn) * (T * T) + idx] : 0.f;
    }
    __syncthreads();

    const int gid = gid0 + tid;
    const int n   = gid / HW4;
    const int p4  = gid - n * HW4;
    const int m   = n - n0;
    const int rn  = NBC - 1 - n;                    // reversed n
    const int b   = rn >> 6;
    const int c   = rn & 63;

    const int stride_s = C * HW4;                   // float4 stride per t/s
    const int base     = (b * T * C + c) * HW4 + p4;
    const float4* xb = (const float4*)x + base;
    float4* ob = (float4*)out + base;

    float4 v[T];
    #pragma unroll
    for (int s = 0; s < T; ++s)
        v[s] = xb[s * stride_s];

    const float* arow = satt[m];
    #pragma unroll
    for (int t = 0; t < T; ++t) {
        float4 a = make_float4(0.f, 0.f, 0.f, 0.f);
        #pragma unroll
        for (int s = 0; s < T; ++s) {
            const float w = arow[t * T + s];
            a.x = fmaf(w, v[s].x, a.x);
            a.y = fmaf(w, v[s].y, a.y);
            a.z = fmaf(w, v[s].z, a.z);
            a.w = fmaf(w, v[s].w, a.w);
        }
        __stcs(&ob[t * stride_s], a);               // streaming store
    }
}

// ---------------------------------------------------------------------------
extern "C" void kernel_launch(void* const* d_in, const int* in_sizes, int n_in,
                              void* d_out, int out_size)
{
    const float* x  = (const float*)d_in[0];
    const float* Wq = (const float*)d_in[1];
    const float* bq = (const float*)d_in[2];
    const float* Wk = (const float*)d_in[3];
    const float* bk = (const float*)d_in[4];
    float* out = (float*)d_out;

    pool_kernel<<<NT, 256>>>(x);
    att_kernel<<<NBC, 256>>>(Wq, bq, Wk, bk);
    av_kernel<<<NCOL / 256, 256>>>(x, out);
}

// round 8
// speedup vs baseline: 1.2830x; 1.0060x over previous
#include <cuda_runtime.h>
#include <cuda_bf16.h>

#define Bb   8
#define T    16
#define C    64
#define Hh   56
#define Ww   56
#define HW   3136          // 56*56
#define HW4  784           // HW/4
#define DIN  64            // 8*8 pooled
#define DOUT 32            // 2*d_t
#define NBC  512           // b*c
#define NT   (NBC * T)     // 8192 (n,t) slices
#define NCOL (NBC * HW4)   // 401408 float4 columns total (= 1568 * 256)

// scratch
__device__ float g_flat[NT * DIN];       // pooled features [n*T+t][64], 2MB
__device__ float g_att[NBC * T * T];     // softmaxed attention, 512KB

// ---------------------------------------------------------------------------
// Kernel 1: pooling, warp-autonomous. One block per (n,t) slice; each of the
// 8 warps owns one bin-row d1 (7 image rows x 56 cols). Lanes<28 accumulate
// float2 column sums over the 7 rows (7 coalesced LDG.64, MLP=7), dump the
// 56 column sums to a per-warp smem strip, then lanes 0-7 each fold 7 column
// sums into one bin. No block barrier, no full-slice smem staging.
// ---------------------------------------------------------------------------
__global__ __launch_bounds__(256)
void pool_kernel(const float* __restrict__ x)
{
    const int nt   = blockIdx.x;        // n*T + t
    const int n    = nt >> 4;
    const int t    = nt & 15;
    const int b    = n >> 6;
    const int c    = n & 63;
    const int wid  = threadIdx.x >> 5;  // d1 = bin row, 0..7
    const int lane = threadIdx.x & 31;

    __shared__ float scol[8][56 + 8];   // per-warp column sums (padded)

    const float* slice = x + ((size_t)(b * T + t) * C + c) * HW;
    const float2* rows = (const float2*)(slice + (7 * wid) * Ww);  // 28 f2/row

    if (lane < 28) {
        float2 s = make_float2(0.f, 0.f);
        #pragma unroll
        for (int dh = 0; dh < 7; ++dh) {
            const float2 v = rows[dh * (Ww / 2) + lane];
            s.x += v.x;
            s.y += v.y;
        }
        scol[wid][2 * lane]     = s.x;
        scol[wid][2 * lane + 1] = s.y;
    }
    __syncwarp();

    if (lane < 8) {
        const float* cs = &scol[wid][7 * lane];
        float a0 = cs[0] + cs[1];
        float a1 = cs[2] + cs[3];
        float a2 = cs[4] + cs[5];
        a0 += cs[6];
        g_flat[nt * DIN + wid * 8 + lane] = (a0 + a1 + a2) * (1.f / 49.f);
    }
}

// ---------------------------------------------------------------------------
// Kernel 2: q/k projection + att + register/shuffle softmax. One block per n.
// ---------------------------------------------------------------------------
__global__ __launch_bounds__(256)
void att_kernel(const float* __restrict__ Wq, const float* __restrict__ bq,
                const float* __restrict__ Wk, const float* __restrict__ bk)
{
    const int n   = blockIdx.x;
    const int tid = threadIdx.x;

    __shared__ float flat[T][DIN];           // 4 KB
    __shared__ float sWq[DIN * DOUT];        // 8 KB
    __shared__ float sWk[DIN * DOUT];        // 8 KB
    __shared__ float sq[T][DOUT + 1];
    __shared__ float sk[T][DOUT + 1];

    for (int i = tid; i < DIN * DOUT; i += 256) {
        sWq[i] = Wq[i];
        sWk[i] = Wk[i];
    }
    for (int i = tid; i < T * DIN; i += 256)
        ((float*)flat)[i] = g_flat[n * T * DIN + i];
    __syncthreads();

    // q = flat@Wq + bq ; k = flat@Wk + bk (2 outputs per thread)
    for (int i = tid; i < T * DOUT; i += 256) {
        const int tt = i >> 5, j = i & 31;
        float aq = bq[j];
        float ak = bk[j];
        #pragma unroll
        for (int d = 0; d < DIN; ++d) {
            const float f = flat[tt][d];
            aq = fmaf(f, sWq[d * DOUT + j], aq);
            ak = fmaf(f, sWk[d * DOUT + j], ak);
        }
        sq[tt][j] = aq;
        sk[tt][j] = ak;
    }
    __syncthreads();

    // logit[i][j] in register of thread tid = i*16 + j
    const int i = tid >> 4, j = tid & 15;
    float s = 0.f;
    #pragma unroll
    for (int d = 0; d < DOUT; ++d)
        s = fmaf(sq[i][d], sk[j][d], s);
    s *= 0.25f;                          // 1/sqrt(16)

    // row softmax via 16-lane shuffle groups
    float m = s;
    #pragma unroll
    for (int k = 8; k >= 1; k >>= 1)
        m = fmaxf(m, __shfl_xor_sync(0xffffffffu, m, k));
    float e = __expf(s - m);
    float ssum = e;
    #pragma unroll
    for (int k = 8; k >= 1; k >>= 1)
        ssum += __shfl_xor_sync(0xffffffffu, ssum, k);

    g_att[n * (T * T) + tid] = e * (1.f / ssum);
}

// ---------------------------------------------------------------------------
// Kernel 3: out[b,t,c,:] = sum_s att[n,t,s] * x[b,s,c,:]
// Flattened grid (1568 full blocks), REVERSED n order for L2 reuse of x
// (pool read ascending; tail of x is still resident). __stcs streaming stores.
// ---------------------------------------------------------------------------
__global__ __launch_bounds__(256)
void av_kernel(const float* __restrict__ x, float* __restrict__ out)
{
    const int tid  = threadIdx.x;
    const int gid0 = blockIdx.x << 8;               // first column of block
    const int n0   = gid0 / HW4;                    // block spans n0 or n0+1

    // stage att rows for the (at most) 2 reversed-n's this block touches
    __shared__ float satt[2][T * T];
    #pragma unroll
    for (int i = tid; i < 2 * T * T; i += 256) {
        const int m   = i >> 8;
        const int idx = i & 255;
        const int nn  = n0 + m;
        satt[m][idx] = (nn < NBC) ? g_att[(NBC - 1 - nn) * (T * T) + idx] : 0.f;
    }
    __syncthreads();

    const int gid = gid0 + tid;
    const int n   = gid / HW4;
    const int p4  = gid - n * HW4;
    const int m   = n - n0;
    const int rn  = NBC - 1 - n;                    // reversed n
    const int b   = rn >> 6;
    const int c   = rn & 63;

    const int stride_s = C * HW4;                   // float4 stride per t/s
    const int base     = (b * T * C + c) * HW4 + p4;
    const float4* xb = (const float4*)x + base;
    float4* ob = (float4*)out + base;

    float4 v[T];
    #pragma unroll
    for (int s = 0; s < T; ++s)
        v[s] = xb[s * stride_s];

    const float* arow = satt[m];
    #pragma unroll
    for (int t = 0; t < T; ++t) {
        float4 a = make_float4(0.f, 0.f, 0.f, 0.f);
        #pragma unroll
        for (int s = 0; s < T; ++s) {
            const float w = arow[t * T + s];
            a.x = fmaf(w, v[s].x, a.x);
            a.y = fmaf(w, v[s].y, a.y);
            a.z = fmaf(w, v[s].z, a.z);
            a.w = fmaf(w, v[s].w, a.w);
        }
        __stcs(&ob[t * stride_s], a);               // streaming store
    }
}

// ---------------------------------------------------------------------------
extern "C" void kernel_launch(void* const* d_in, const int* in_sizes, int n_in,
                              void* d_out, int out_size)
{
    const float* x  = (const float*)d_in[0];
    const float* Wq = (const float*)d_in[1];
    const float* bq = (const float*)d_in[2];
    const float* Wk = (const float*)d_in[3];
    const float* bk = (const float*)d_in[4];
    float* out = (float*)d_out;

    pool_kernel<<<NT, 256>>>(x);
    att_kernel<<<NBC, 256>>>(Wq, bq, Wk, bk);
    av_kernel<<<NCOL / 256, 256>>>(x, out);
}